// round 9
// baseline (speedup 1.0000x reference)
#include <cuda_runtime.h>

// 2D Haar DWT, fp32, x:[16,64,512,512] -> out:[4,16,64,256,256]
// Pure streaming, DRAM-bound. Chassis: R6 one-shot grid, dense 2 output
// cols/thread, block=256 (307.0us, 88.4% DRAM, 7.0 TB/s).
// Scan results: per-thread width {2 best, 4, 8 worst}, block {128,256} ~equal,
// persistent grids strictly worse, __stcs neutral. R9 (last single variable):
// __ldcs evict-first on the input stream.
//
//   ll = 0.5*(a+b+c+d)   lh = 0.5*(a+b-c-d)
//   hl = 0.5*(a-b+c-d)   hh = 0.5*(a-b-c+d)

static constexpr int W_IN  = 512;
static constexpr int W_OUT = 256;
static constexpr int H_OUT = 256;
static constexpr int PLANES = 16 * 64;                                  // 1024
static constexpr long long IN_PLANE  = (long long)W_IN * 512;           // 262144
static constexpr long long OUT_PLANE = (long long)W_OUT * H_OUT;        // 65536
static constexpr long long BAND_STRIDE = (long long)PLANES * OUT_PLANE; // 67,108,864

__global__ __launch_bounds__(256) void haar_dwt_kernel(
    const float* __restrict__ x, float* __restrict__ out)
{
    unsigned idx = blockIdx.x * 256u + threadIdx.x;   // 0 .. 33,554,431
    unsigned tx = idx & 127u;          // 2-col group (input cols 4tx..4tx+3)
    unsigned h  = (idx >> 7) & 255u;   // output row
    unsigned p  = idx >> 15;           // plane 0..1023

    // Dense: thread loads 4 consecutive floats (16B) from each of rows 2h, 2h+1.
    const float* base = x + (size_t)p * IN_PLANE + (size_t)(2u * h) * W_IN + tx * 4u;
    float4 c0 = __ldcs(reinterpret_cast<const float4*>(base));
    float4 c1 = __ldcs(reinterpret_cast<const float4*>(base + W_IN));

    float2 ll, lh, hl, hh;
    {
        float sT = c0.x + c0.y, dT = c0.x - c0.y;
        float sB = c1.x + c1.y, dB = c1.x - c1.y;
        ll.x = 0.5f * (sT + sB); lh.x = 0.5f * (sT - sB);
        hl.x = 0.5f * (dT + dB); hh.x = 0.5f * (dT - dB);
    }
    {
        float sT = c0.z + c0.w, dT = c0.z - c0.w;
        float sB = c1.z + c1.w, dB = c1.z - c1.w;
        ll.y = 0.5f * (sT + sB); lh.y = 0.5f * (sT - sB);
        hl.y = 0.5f * (dT + dB); hh.y = 0.5f * (dT - dB);
    }

    float* o = out + (size_t)p * OUT_PLANE + (size_t)h * W_OUT + tx * 2u;
    *reinterpret_cast<float2*>(o)                   = ll;
    *reinterpret_cast<float2*>(o + BAND_STRIDE)     = lh;
    *reinterpret_cast<float2*>(o + 2 * BAND_STRIDE) = hl;
    *reinterpret_cast<float2*>(o + 3 * BAND_STRIDE) = hh;
}

extern "C" void kernel_launch(void* const* d_in, const int* in_sizes, int n_in,
                              void* d_out, int out_size) {
    const float* x = (const float*)d_in[0];
    float* out = (float*)d_out;
    // total threads = 1024 planes * 256 rows * 128 groups = 33,554,432
    unsigned total = (unsigned)PLANES * H_OUT * (W_OUT / 2);
    haar_dwt_kernel<<<total / 256, 256>>>(x, out);
}

// round 10
// speedup vs baseline: 1.0246x; 1.0246x over previous
#include <cuda_runtime.h>

// 2D Haar DWT, fp32, x:[16,64,512,512] -> out:[4,16,64,256,256]
// FINAL (R6 chassis). Pure streaming, DRAM-bound: 1 GiB read + 1 GiB write
// (theoretical traffic minimum). Achieves 7.0 TB/s = 88.4% of HBM spec.
//
// Design: one-shot grid (CTA drain/refill is the pipeline — persistent
// variants regress), dense 2 output cols/thread (each lane loads 16B at 16B
// stride from each of 2 input rows: one fully dense 512B warp access per
// LDG.128), default cache policy (__ldcs/__stcs tested: neutral-to-negative),
// block=256, 21 regs.
//
// Per 2x2 block [[a,b],[c,d]], lo=[r,r], hi=[r,-r], r=1/sqrt(2):
//   ll = 0.5*(a+b+c+d)   lh = 0.5*(a+b-c-d)
//   hl = 0.5*(a-b+c-d)   hh = 0.5*(a-b-c+d)

static constexpr int W_IN  = 512;
static constexpr int W_OUT = 256;
static constexpr int H_OUT = 256;
static constexpr int PLANES = 16 * 64;                                  // 1024
static constexpr long long IN_PLANE  = (long long)W_IN * 512;           // 262144
static constexpr long long OUT_PLANE = (long long)W_OUT * H_OUT;        // 65536
static constexpr long long BAND_STRIDE = (long long)PLANES * OUT_PLANE; // 67,108,864

__global__ __launch_bounds__(256) void haar_dwt_kernel(
    const float* __restrict__ x, float* __restrict__ out)
{
    unsigned idx = blockIdx.x * 256u + threadIdx.x;   // 0 .. 33,554,431
    unsigned tx = idx & 127u;          // 2-col group (input cols 4tx..4tx+3)
    unsigned h  = (idx >> 7) & 255u;   // output row
    unsigned p  = idx >> 15;           // plane 0..1023

    // Dense: thread loads 4 consecutive floats (16B) from each of rows 2h, 2h+1.
    const float* base = x + (size_t)p * IN_PLANE + (size_t)(2u * h) * W_IN + tx * 4u;
    float4 c0 = *reinterpret_cast<const float4*>(base);
    float4 c1 = *reinterpret_cast<const float4*>(base + W_IN);

    float2 ll, lh, hl, hh;
    {
        float sT = c0.x + c0.y, dT = c0.x - c0.y;
        float sB = c1.x + c1.y, dB = c1.x - c1.y;
        ll.x = 0.5f * (sT + sB); lh.x = 0.5f * (sT - sB);
        hl.x = 0.5f * (dT + dB); hh.x = 0.5f * (dT - dB);
    }
    {
        float sT = c0.z + c0.w, dT = c0.z - c0.w;
        float sB = c1.z + c1.w, dB = c1.z - c1.w;
        ll.y = 0.5f * (sT + sB); lh.y = 0.5f * (sT - sB);
        hl.y = 0.5f * (dT + dB); hh.y = 0.5f * (dT - dB);
    }

    float* o = out + (size_t)p * OUT_PLANE + (size_t)h * W_OUT + tx * 2u;
    *reinterpret_cast<float2*>(o)                   = ll;
    *reinterpret_cast<float2*>(o + BAND_STRIDE)     = lh;
    *reinterpret_cast<float2*>(o + 2 * BAND_STRIDE) = hl;
    *reinterpret_cast<float2*>(o + 3 * BAND_STRIDE) = hh;
}

extern "C" void kernel_launch(void* const* d_in, const int* in_sizes, int n_in,
                              void* d_out, int out_size) {
    const float* x = (const float*)d_in[0];
    float* out = (float*)d_out;
    // total threads = 1024 planes * 256 rows * 128 groups = 33,554,432
    unsigned total = (unsigned)PLANES * H_OUT * (W_OUT / 2);
    haar_dwt_kernel<<<total / 256, 256>>>(x, out);
}